// round 1
// baseline (speedup 1.0000x reference)
#include <cuda_runtime.h>
#include <stdint.h>

#define B_USERS     4096
#define D_DIM       64
#define NNZ_CNT     204800
#define N_PAIRS     1048576
#define NUM_ITEMS_C 100000
#define REG_ROWS    (NUM_ITEMS_C + B_USERS + 1)   // items + user rows + en_offset row

// Scratch (no cudaMalloc allowed)
__device__ float         g_hidden[B_USERS * D_DIM];
__device__ unsigned char g_mask[NUM_ITEMS_C];

// ---------------- Threefry-2x32 (JAX partitionable path) ----------------
__device__ __forceinline__ uint32_t rotl32(uint32_t x, int r) {
    return (x << r) | (x >> (32 - r));
}

// key = (0, 42); counter = 64-bit i -> (x0 = hi32 = 0, x1 = lo32 = i)
// returns x0 ^ x1 (32-bit partitionable random bits)
__device__ __forceinline__ uint32_t threefry_bits(uint32_t ctr_lo) {
    const uint32_t ks0 = 0u, ks1 = 42u;
    const uint32_t ks2 = ks0 ^ ks1 ^ 0x1BD11BDAu;
    uint32_t x0 = 0u  + ks0;
    uint32_t x1 = ctr_lo + ks1;

    // round group 1 (13,15,26,6)
    x0 += x1; x1 = rotl32(x1, 13); x1 ^= x0;
    x0 += x1; x1 = rotl32(x1, 15); x1 ^= x0;
    x0 += x1; x1 = rotl32(x1, 26); x1 ^= x0;
    x0 += x1; x1 = rotl32(x1,  6); x1 ^= x0;
    x0 += ks1; x1 += ks2 + 1u;
    // group 2 (17,29,16,24)
    x0 += x1; x1 = rotl32(x1, 17); x1 ^= x0;
    x0 += x1; x1 = rotl32(x1, 29); x1 ^= x0;
    x0 += x1; x1 = rotl32(x1, 16); x1 ^= x0;
    x0 += x1; x1 = rotl32(x1, 24); x1 ^= x0;
    x0 += ks2; x1 += ks0 + 2u;
    // group 3 (13,15,26,6)
    x0 += x1; x1 = rotl32(x1, 13); x1 ^= x0;
    x0 += x1; x1 = rotl32(x1, 15); x1 ^= x0;
    x0 += x1; x1 = rotl32(x1, 26); x1 ^= x0;
    x0 += x1; x1 = rotl32(x1,  6); x1 ^= x0;
    x0 += ks0; x1 += ks1 + 3u;
    // group 4 (17,29,16,24)
    x0 += x1; x1 = rotl32(x1, 17); x1 ^= x0;
    x0 += x1; x1 = rotl32(x1, 29); x1 ^= x0;
    x0 += x1; x1 = rotl32(x1, 16); x1 ^= x0;
    x0 += x1; x1 = rotl32(x1, 24); x1 ^= x0;
    x0 += ks1; x1 += ks2 + 4u;
    // group 5 (13,15,26,6)
    x0 += x1; x1 = rotl32(x1, 13); x1 ^= x0;
    x0 += x1; x1 = rotl32(x1, 15); x1 ^= x0;
    x0 += x1; x1 = rotl32(x1, 26); x1 ^= x0;
    x0 += x1; x1 = rotl32(x1,  6); x1 ^= x0;
    x0 += ks2; x1 += ks0 + 5u;

    return x0 ^ x1;
}

// keep-mask: uniform = bitcast((bits>>9)|0x3f800000) - 1 ; keep if u < 0.8f
__device__ __forceinline__ bool keep_mask(uint32_t i) {
    uint32_t bits = threefry_bits(i);
    float u = __uint_as_float((bits >> 9) | 0x3f800000u) - 1.0f;
    return u < 0.8f;
}

// ---------------- Kernels ----------------
__global__ void k_init(float* reg_out) {
    int idx = blockIdx.x * blockDim.x + threadIdx.x;
    if (idx < B_USERS * D_DIM) g_hidden[idx] = 0.0f;
    if (idx < NUM_ITEMS_C)     g_mask[idx]   = 0;
    if (idx == 0 && reg_out)   *reg_out      = 0.0f;
}

// 16 threads per nnz; each lane handles one float4 of the 64-wide row.
__global__ void k_scatter(const int* __restrict__ sp_row,
                          const int* __restrict__ sp_col,
                          const float* __restrict__ en_emb) {
    int t    = blockIdx.x * blockDim.x + threadIdx.x;
    int i    = t >> 4;
    int lane = t & 15;
    if (i >= NNZ_CNT) return;
    if (!keep_mask((uint32_t)i)) return;

    int row = __ldg(sp_row + i);
    int col = __ldg(sp_col + i);
    float4 e = __ldg((const float4*)en_emb + (size_t)col * 16 + lane);
    float* hp = g_hidden + (size_t)row * 64 + lane * 4;
    atomicAdd(hp + 0, 1.25f * e.x);
    atomicAdd(hp + 1, 1.25f * e.y);
    atomicAdd(hp + 2, 1.25f * e.z);
    atomicAdd(hp + 3, 1.25f * e.w);
}

__global__ void k_hidden(const int* __restrict__ user_ids,
                         const float* __restrict__ user_emb,
                         const float* __restrict__ en_offset) {
    int idx = blockIdx.x * blockDim.x + threadIdx.x;
    if (idx >= B_USERS * D_DIM) return;
    int b = idx >> 6;
    int d = idx & 63;
    float v = g_hidden[idx] + __ldg(user_emb + (size_t)__ldg(user_ids + b) * 64 + d)
                            + __ldg(en_offset + d);
    g_hidden[idx] = tanhf(v);
}

// 16 threads per pair: coalesced float4 row loads + intra-group shuffle reduce.
__global__ void k_decode(const int* __restrict__ bat_idx,
                         const int* __restrict__ bat_items,
                         const float* __restrict__ de_emb,
                         const float* __restrict__ de_bias,
                         float* __restrict__ out) {
    int t    = blockIdx.x * blockDim.x + threadIdx.x;
    int n    = t >> 4;
    int lane = t & 15;
    // grid is exact: N_PAIRS*16 threads, no bounds check needed, all lanes active
    int b  = __ldg(bat_idx + n);
    int it = __ldg(bat_items + n);

    float4 h = *((const float4*)g_hidden + (size_t)b * 16 + lane);
    float4 e = __ldg((const float4*)de_emb + (size_t)it * 16 + lane);
    float p = h.x * e.x + h.y * e.y + h.z * e.z + h.w * e.w;
    p += __shfl_xor_sync(0xffffffffu, p, 1);
    p += __shfl_xor_sync(0xffffffffu, p, 2);
    p += __shfl_xor_sync(0xffffffffu, p, 4);
    p += __shfl_xor_sync(0xffffffffu, p, 8);
    if (lane == 0) {
        out[n] = p + __ldg(de_bias + it);
        g_mask[it] = 1;   // idempotent
    }
}

// 16 threads per row over items + user rows + one en_offset row.
__global__ void k_reg(const float* __restrict__ en_emb,
                      const float* __restrict__ en_offset,
                      const float* __restrict__ de_emb,
                      const float* __restrict__ de_bias,
                      const float* __restrict__ user_emb,
                      const int*   __restrict__ user_ids,
                      float* __restrict__ reg_out) {
    __shared__ float bacc;
    if (threadIdx.x == 0) bacc = 0.0f;
    __syncthreads();

    int t    = blockIdx.x * blockDim.x + threadIdx.x;
    int r    = t >> 4;
    int lane = t & 15;
    float c = 0.0f;

    if (r < NUM_ITEMS_C) {
        if (g_mask[r]) {
            float4 e = __ldg((const float4*)en_emb + (size_t)r * 16 + lane);
            float4 d = __ldg((const float4*)de_emb + (size_t)r * 16 + lane);
            c = e.x * e.x + e.y * e.y + e.z * e.z + e.w * e.w
              + d.x * d.x + d.y * d.y + d.z * d.z + d.w * d.w;
            if (lane == 0) { float bb = __ldg(de_bias + r); c += bb * bb; }
        }
    } else if (r < NUM_ITEMS_C + B_USERS) {
        int b = r - NUM_ITEMS_C;
        float4 u = __ldg((const float4*)user_emb + (size_t)__ldg(user_ids + b) * 16 + lane);
        c = u.x * u.x + u.y * u.y + u.z * u.z + u.w * u.w;
    } else if (r == NUM_ITEMS_C + B_USERS) {
        float4 o = __ldg((const float4*)en_offset + lane);
        c = o.x * o.x + o.y * o.y + o.z * o.z + o.w * o.w;
    }
    // all 32 lanes of every warp reach here (no early return) -> full-mask shuffles ok
    c += __shfl_xor_sync(0xffffffffu, c, 1);
    c += __shfl_xor_sync(0xffffffffu, c, 2);
    c += __shfl_xor_sync(0xffffffffu, c, 4);
    c += __shfl_xor_sync(0xffffffffu, c, 8);
    if (lane == 0 && c != 0.0f) atomicAdd(&bacc, c);
    __syncthreads();
    if (threadIdx.x == 0 && bacc != 0.0f) atomicAdd(reg_out, 0.5f * bacc);
}

extern "C" void kernel_launch(void* const* d_in, const int* in_sizes, int n_in,
                              void* d_out, int out_size) {
    const int*   user_ids  = (const int*)d_in[0];
    const int*   bat_idx   = (const int*)d_in[1];
    const int*   sp_row    = (const int*)d_in[2];
    const int*   sp_col    = (const int*)d_in[3];
    const int*   bat_items = (const int*)d_in[4];
    const float* en_emb    = (const float*)d_in[5];
    const float* en_offset = (const float*)d_in[6];
    const float* de_emb    = (const float*)d_in[7];
    const float* de_bias   = (const float*)d_in[8];
    const float* user_emb  = (const float*)d_in[9];
    float* out = (float*)d_out;
    float* reg_out = (out_size > N_PAIRS) ? (out + N_PAIRS) : nullptr;

    k_init<<<(B_USERS * D_DIM + 255) / 256, 256>>>(reg_out);
    k_scatter<<<(NNZ_CNT * 16) / 256, 256>>>(sp_row, sp_col, en_emb);
    k_hidden<<<(B_USERS * D_DIM) / 256, 256>>>(user_ids, user_emb, en_offset);
    k_decode<<<(N_PAIRS * 16) / 256, 256>>>(bat_idx, bat_items, de_emb, de_bias, out);
    if (reg_out) {
        k_reg<<<(REG_ROWS * 16 + 255) / 256, 256>>>(en_emb, en_offset, de_emb,
                                                    de_bias, user_emb, user_ids, reg_out);
    }
}

// round 2
// speedup vs baseline: 1.1175x; 1.1175x over previous
#include <cuda_runtime.h>
#include <stdint.h>

#define B_USERS     4096
#define D_DIM       64
#define NNZ_CNT     204800
#define N_PAIRS     1048576
#define NUM_ITEMS_C 100000
#define REG_ROWS    (NUM_ITEMS_C + B_USERS + 1)   // items + user rows + en_offset row

// Scratch (no cudaMalloc allowed)
__device__ float         g_hidden[B_USERS * D_DIM];
__device__ unsigned char g_mask[NUM_ITEMS_C];

// ---------------- Threefry-2x32 (JAX partitionable path) ----------------
__device__ __forceinline__ uint32_t rotl32(uint32_t x, int r) {
    return (x << r) | (x >> (32 - r));
}

__device__ __forceinline__ uint32_t threefry_bits(uint32_t ctr_lo) {
    const uint32_t ks0 = 0u, ks1 = 42u;
    const uint32_t ks2 = ks0 ^ ks1 ^ 0x1BD11BDAu;
    uint32_t x0 = 0u  + ks0;
    uint32_t x1 = ctr_lo + ks1;

    x0 += x1; x1 = rotl32(x1, 13); x1 ^= x0;
    x0 += x1; x1 = rotl32(x1, 15); x1 ^= x0;
    x0 += x1; x1 = rotl32(x1, 26); x1 ^= x0;
    x0 += x1; x1 = rotl32(x1,  6); x1 ^= x0;
    x0 += ks1; x1 += ks2 + 1u;
    x0 += x1; x1 = rotl32(x1, 17); x1 ^= x0;
    x0 += x1; x1 = rotl32(x1, 29); x1 ^= x0;
    x0 += x1; x1 = rotl32(x1, 16); x1 ^= x0;
    x0 += x1; x1 = rotl32(x1, 24); x1 ^= x0;
    x0 += ks2; x1 += ks0 + 2u;
    x0 += x1; x1 = rotl32(x1, 13); x1 ^= x0;
    x0 += x1; x1 = rotl32(x1, 15); x1 ^= x0;
    x0 += x1; x1 = rotl32(x1, 26); x1 ^= x0;
    x0 += x1; x1 = rotl32(x1,  6); x1 ^= x0;
    x0 += ks0; x1 += ks1 + 3u;
    x0 += x1; x1 = rotl32(x1, 17); x1 ^= x0;
    x0 += x1; x1 = rotl32(x1, 29); x1 ^= x0;
    x0 += x1; x1 = rotl32(x1, 16); x1 ^= x0;
    x0 += x1; x1 = rotl32(x1, 24); x1 ^= x0;
    x0 += ks1; x1 += ks2 + 4u;
    x0 += x1; x1 = rotl32(x1, 13); x1 ^= x0;
    x0 += x1; x1 = rotl32(x1, 15); x1 ^= x0;
    x0 += x1; x1 = rotl32(x1, 26); x1 ^= x0;
    x0 += x1; x1 = rotl32(x1,  6); x1 ^= x0;
    x0 += ks2; x1 += ks0 + 5u;

    return x0 ^ x1;
}

__device__ __forceinline__ bool keep_mask(uint32_t i) {
    uint32_t bits = threefry_bits(i);
    float u = __uint_as_float((bits >> 9) | 0x3f800000u) - 1.0f;
    return u < 0.8f;
}

// ---------------- Kernels ----------------
__global__ void k_init(float* reg_out) {
    int idx = blockIdx.x * blockDim.x + threadIdx.x;
    if (idx < B_USERS * D_DIM) g_hidden[idx] = 0.0f;
    if (idx < NUM_ITEMS_C)     g_mask[idx]   = 0;
    if (idx == 0 && reg_out)   *reg_out      = 0.0f;
}

// 16 threads per nnz; each lane handles one float4 of the 64-wide row.
__global__ void k_scatter(const int* __restrict__ sp_row,
                          const int* __restrict__ sp_col,
                          const float* __restrict__ en_emb) {
    int t    = blockIdx.x * blockDim.x + threadIdx.x;
    int i    = t >> 4;
    int lane = t & 15;
    if (i >= NNZ_CNT) return;
    if (!keep_mask((uint32_t)i)) return;

    int row = __ldg(sp_row + i);
    int col = __ldg(sp_col + i);
    float4 e = __ldg((const float4*)en_emb + (size_t)col * 16 + lane);
    float* hp = g_hidden + (size_t)row * 64 + lane * 4;
    atomicAdd(hp + 0, 1.25f * e.x);
    atomicAdd(hp + 1, 1.25f * e.y);
    atomicAdd(hp + 2, 1.25f * e.z);
    atomicAdd(hp + 3, 1.25f * e.w);
}

__global__ void k_hidden(const int* __restrict__ user_ids,
                         const float* __restrict__ user_emb,
                         const float* __restrict__ en_offset) {
    int idx = blockIdx.x * blockDim.x + threadIdx.x;
    if (idx >= B_USERS * D_DIM) return;
    int b = idx >> 6;
    int d = idx & 63;
    float v = g_hidden[idx] + __ldg(user_emb + (size_t)__ldg(user_ids + b) * 64 + d)
                            + __ldg(en_offset + d);
    g_hidden[idx] = tanhf(v);
}

__device__ __forceinline__ float dot4(float4 a, float4 b) {
    return a.x * b.x + a.y * b.y + a.z * b.z + a.w * b.w;
}

// 4 lanes per pair, 8 pairs per warp. Each lane issues 8 independent LDG.128
// (4 from hidden row, 4 from de_emb row) -> MLP ~8 per thread, hiding L2 latency.
__global__ void __launch_bounds__(256) k_decode(
        const int* __restrict__ bat_idx,
        const int* __restrict__ bat_items,
        const float* __restrict__ de_emb,
        const float* __restrict__ de_bias,
        float* __restrict__ out) {
    int t    = blockIdx.x * blockDim.x + threadIdx.x;
    int n    = t >> 2;          // pair index (N_PAIRS*4 threads exactly)
    int ql   = t & 3;           // quarter-lane within pair

    int b  = __ldg(bat_idx + n);
    int it = __ldg(bat_items + n);

    const float4* hp = (const float4*)g_hidden + (size_t)b  * 16 + ql;
    const float4* ep = (const float4*)de_emb   + (size_t)it * 16 + ql;

    float4 h0 = hp[0],        h1 = hp[4],        h2 = hp[8],        h3 = hp[12];
    float4 e0 = __ldg(ep + 0), e1 = __ldg(ep + 4), e2 = __ldg(ep + 8), e3 = __ldg(ep + 12);

    float p = dot4(h0, e0) + dot4(h1, e1) + dot4(h2, e2) + dot4(h3, e3);
    p += __shfl_xor_sync(0xffffffffu, p, 1);
    p += __shfl_xor_sync(0xffffffffu, p, 2);

    if (ql == 0) {
        out[n] = p + __ldg(de_bias + it);
        g_mask[it] = 1;   // idempotent
    }
}

// 16 threads per row over items + user rows + one en_offset row.
__global__ void k_reg(const float* __restrict__ en_emb,
                      const float* __restrict__ en_offset,
                      const float* __restrict__ de_emb,
                      const float* __restrict__ de_bias,
                      const float* __restrict__ user_emb,
                      const int*   __restrict__ user_ids,
                      float* __restrict__ reg_out) {
    __shared__ float bacc;
    if (threadIdx.x == 0) bacc = 0.0f;
    __syncthreads();

    int t    = blockIdx.x * blockDim.x + threadIdx.x;
    int r    = t >> 4;
    int lane = t & 15;
    float c = 0.0f;

    if (r < NUM_ITEMS_C) {
        if (g_mask[r]) {
            float4 e = __ldg((const float4*)en_emb + (size_t)r * 16 + lane);
            float4 d = __ldg((const float4*)de_emb + (size_t)r * 16 + lane);
            c = e.x * e.x + e.y * e.y + e.z * e.z + e.w * e.w
              + d.x * d.x + d.y * d.y + d.z * d.z + d.w * d.w;
            if (lane == 0) { float bb = __ldg(de_bias + r); c += bb * bb; }
        }
    } else if (r < NUM_ITEMS_C + B_USERS) {
        int b = r - NUM_ITEMS_C;
        float4 u = __ldg((const float4*)user_emb + (size_t)__ldg(user_ids + b) * 16 + lane);
        c = u.x * u.x + u.y * u.y + u.z * u.z + u.w * u.w;
    } else if (r == NUM_ITEMS_C + B_USERS) {
        float4 o = __ldg((const float4*)en_offset + lane);
        c = o.x * o.x + o.y * o.y + o.z * o.z + o.w * o.w;
    }
    c += __shfl_xor_sync(0xffffffffu, c, 1);
    c += __shfl_xor_sync(0xffffffffu, c, 2);
    c += __shfl_xor_sync(0xffffffffu, c, 4);
    c += __shfl_xor_sync(0xffffffffu, c, 8);
    if (lane == 0 && c != 0.0f) atomicAdd(&bacc, c);
    __syncthreads();
    if (threadIdx.x == 0 && bacc != 0.0f) atomicAdd(reg_out, 0.5f * bacc);
}

extern "C" void kernel_launch(void* const* d_in, const int* in_sizes, int n_in,
                              void* d_out, int out_size) {
    const int*   user_ids  = (const int*)d_in[0];
    const int*   bat_idx   = (const int*)d_in[1];
    const int*   sp_row    = (const int*)d_in[2];
    const int*   sp_col    = (const int*)d_in[3];
    const int*   bat_items = (const int*)d_in[4];
    const float* en_emb    = (const float*)d_in[5];
    const float* en_offset = (const float*)d_in[6];
    const float* de_emb    = (const float*)d_in[7];
    const float* de_bias   = (const float*)d_in[8];
    const float* user_emb  = (const float*)d_in[9];
    float* out = (float*)d_out;
    float* reg_out = (out_size > N_PAIRS) ? (out + N_PAIRS) : nullptr;

    k_init<<<(B_USERS * D_DIM + 255) / 256, 256>>>(reg_out);
    k_scatter<<<(NNZ_CNT * 16) / 256, 256>>>(sp_row, sp_col, en_emb);
    k_hidden<<<(B_USERS * D_DIM) / 256, 256>>>(user_ids, user_emb, en_offset);
    k_decode<<<(N_PAIRS * 4) / 256, 256>>>(bat_idx, bat_items, de_emb, de_bias, out);
    if (reg_out) {
        k_reg<<<(REG_ROWS * 16 + 255) / 256, 256>>>(en_emb, en_offset, de_emb,
                                                    de_bias, user_emb, user_ids, reg_out);
    }
}

// round 3
// speedup vs baseline: 1.3684x; 1.2245x over previous
#include <cuda_runtime.h>
#include <stdint.h>

#define B_USERS     4096
#define D_DIM       64
#define NNZ_CNT     204800
#define N_PAIRS     1048576
#define NUM_ITEMS_C 100000
#define REG_ROWS    (NUM_ITEMS_C + B_USERS + 1)

// Scratch (no cudaMalloc allowed)
__device__ float         g_hidden[B_USERS * D_DIM];
__device__ unsigned char g_mask[NUM_ITEMS_C];
__device__ uint32_t      g_keepw[NNZ_CNT / 32];   // 6400 words, bit per nnz

// ---------------- Threefry-2x32 (JAX partitionable path) ----------------
__device__ __forceinline__ uint32_t rotl32(uint32_t x, int r) {
    return (x << r) | (x >> (32 - r));
}

__device__ __forceinline__ uint32_t threefry_bits(uint32_t ctr_lo) {
    const uint32_t ks0 = 0u, ks1 = 42u;
    const uint32_t ks2 = ks0 ^ ks1 ^ 0x1BD11BDAu;
    uint32_t x0 = 0u  + ks0;
    uint32_t x1 = ctr_lo + ks1;

    x0 += x1; x1 = rotl32(x1, 13); x1 ^= x0;
    x0 += x1; x1 = rotl32(x1, 15); x1 ^= x0;
    x0 += x1; x1 = rotl32(x1, 26); x1 ^= x0;
    x0 += x1; x1 = rotl32(x1,  6); x1 ^= x0;
    x0 += ks1; x1 += ks2 + 1u;
    x0 += x1; x1 = rotl32(x1, 17); x1 ^= x0;
    x0 += x1; x1 = rotl32(x1, 29); x1 ^= x0;
    x0 += x1; x1 = rotl32(x1, 16); x1 ^= x0;
    x0 += x1; x1 = rotl32(x1, 24); x1 ^= x0;
    x0 += ks2; x1 += ks0 + 2u;
    x0 += x1; x1 = rotl32(x1, 13); x1 ^= x0;
    x0 += x1; x1 = rotl32(x1, 15); x1 ^= x0;
    x0 += x1; x1 = rotl32(x1, 26); x1 ^= x0;
    x0 += x1; x1 = rotl32(x1,  6); x1 ^= x0;
    x0 += ks0; x1 += ks1 + 3u;
    x0 += x1; x1 = rotl32(x1, 17); x1 ^= x0;
    x0 += x1; x1 = rotl32(x1, 29); x1 ^= x0;
    x0 += x1; x1 = rotl32(x1, 16); x1 ^= x0;
    x0 += x1; x1 = rotl32(x1, 24); x1 ^= x0;
    x0 += ks1; x1 += ks2 + 4u;
    x0 += x1; x1 = rotl32(x1, 13); x1 ^= x0;
    x0 += x1; x1 = rotl32(x1, 15); x1 ^= x0;
    x0 += x1; x1 = rotl32(x1, 26); x1 ^= x0;
    x0 += x1; x1 = rotl32(x1,  6); x1 ^= x0;
    x0 += ks2; x1 += ks0 + 5u;

    return x0 ^ x1;
}

// ---------------- Kernels ----------------
__global__ void k_init(float* reg_out) {
    int idx = blockIdx.x * blockDim.x + threadIdx.x;
    if (idx < B_USERS * D_DIM) g_hidden[idx] = 0.0f;
    if (idx < NUM_ITEMS_C)     g_mask[idx]   = 0;
    if (idx == 0 && reg_out)   *reg_out      = 0.0f;
}

// One thread per nnz computes keep bit; warp ballots into one word.
__global__ void k_mask() {
    int i = blockIdx.x * blockDim.x + threadIdx.x;   // exact: NNZ_CNT threads
    uint32_t bits = threefry_bits((uint32_t)i);
    float u = __uint_as_float((bits >> 9) | 0x3f800000u) - 1.0f;
    uint32_t ballot = __ballot_sync(0xffffffffu, u < 0.8f);
    if ((threadIdx.x & 31) == 0) g_keepw[i >> 5] = ballot;
}

// 16 lanes per nnz; each lane one float4 -> one REDG.128 per lane.
__global__ void k_scatter(const int* __restrict__ sp_row,
                          const int* __restrict__ sp_col,
                          const float* __restrict__ en_emb) {
    int t    = blockIdx.x * blockDim.x + threadIdx.x;
    int i    = t >> 4;
    int lane = t & 15;
    if (!((g_keepw[i >> 5] >> (i & 31)) & 1u)) return;

    int row = __ldg(sp_row + i);
    int col = __ldg(sp_col + i);
    float4 e = __ldg((const float4*)en_emb + (size_t)col * 16 + lane);
    float4 v = make_float4(1.25f * e.x, 1.25f * e.y, 1.25f * e.z, 1.25f * e.w);
    atomicAdd((float4*)(g_hidden + (size_t)row * 64 + lane * 4), v);
}

__global__ void k_hidden(const int* __restrict__ user_ids,
                         const float* __restrict__ user_emb,
                         const float* __restrict__ en_offset) {
    int idx = blockIdx.x * blockDim.x + threadIdx.x;
    if (idx >= B_USERS * D_DIM) return;
    int b = idx >> 6;
    int d = idx & 63;
    float v = g_hidden[idx] + __ldg(user_emb + (size_t)__ldg(user_ids + b) * 64 + d)
                            + __ldg(en_offset + d);
    g_hidden[idx] = tanhf(v);
}

__device__ __forceinline__ float dot4(float4 a, float4 b) {
    return a.x * b.x + a.y * b.y + a.z * b.z + a.w * b.w;
}

// 8 lanes per pair, 4 pairs per warp. Lanes 0..7 cover one full 128B line per
// load instruction (wavefront-optimal); each lane has 4 independent LDG.128.
__global__ void __launch_bounds__(256) k_decode(
        const int* __restrict__ bat_idx,
        const int* __restrict__ bat_items,
        const float* __restrict__ de_emb,
        const float* __restrict__ de_bias,
        float* __restrict__ out) {
    int t = blockIdx.x * blockDim.x + threadIdx.x;
    int n = t >> 3;             // pair index (N_PAIRS*8 threads exactly)
    int l = t & 7;              // lane within pair

    int b  = __ldg(bat_idx + n);
    int it = __ldg(bat_items + n);

    const float4* hp = (const float4*)g_hidden + (size_t)b  * 16;
    const float4* ep = (const float4*)de_emb   + (size_t)it * 16;

    float4 h0 = hp[l],            h1 = hp[l + 8];
    float4 e0 = __ldg(ep + l),    e1 = __ldg(ep + l + 8);

    float p = dot4(h0, e0) + dot4(h1, e1);
    p += __shfl_xor_sync(0xffffffffu, p, 1);
    p += __shfl_xor_sync(0xffffffffu, p, 2);
    p += __shfl_xor_sync(0xffffffffu, p, 4);

    if (l == 0) {
        out[n] = p + __ldg(de_bias + it);
        g_mask[it] = 1;   // idempotent
    }
}

// 16 threads per row over items + user rows + one en_offset row.
__global__ void k_reg(const float* __restrict__ en_emb,
                      const float* __restrict__ en_offset,
                      const float* __restrict__ de_emb,
                      const float* __restrict__ de_bias,
                      const float* __restrict__ user_emb,
                      const int*   __restrict__ user_ids,
                      float* __restrict__ reg_out) {
    __shared__ float bacc;
    if (threadIdx.x == 0) bacc = 0.0f;
    __syncthreads();

    int t    = blockIdx.x * blockDim.x + threadIdx.x;
    int r    = t >> 4;
    int lane = t & 15;
    float c = 0.0f;

    if (r < NUM_ITEMS_C) {
        if (g_mask[r]) {
            float4 e = __ldg((const float4*)en_emb + (size_t)r * 16 + lane);
            float4 d = __ldg((const float4*)de_emb + (size_t)r * 16 + lane);
            c = e.x * e.x + e.y * e.y + e.z * e.z + e.w * e.w
              + d.x * d.x + d.y * d.y + d.z * d.z + d.w * d.w;
            if (lane == 0) { float bb = __ldg(de_bias + r); c += bb * bb; }
        }
    } else if (r < NUM_ITEMS_C + B_USERS) {
        int b = r - NUM_ITEMS_C;
        float4 u = __ldg((const float4*)user_emb + (size_t)__ldg(user_ids + b) * 16 + lane);
        c = u.x * u.x + u.y * u.y + u.z * u.z + u.w * u.w;
    } else if (r == NUM_ITEMS_C + B_USERS) {
        float4 o = __ldg((const float4*)en_offset + lane);
        c = o.x * o.x + o.y * o.y + o.z * o.z + o.w * o.w;
    }
    c += __shfl_xor_sync(0xffffffffu, c, 1);
    c += __shfl_xor_sync(0xffffffffu, c, 2);
    c += __shfl_xor_sync(0xffffffffu, c, 4);
    c += __shfl_xor_sync(0xffffffffu, c, 8);
    if (lane == 0 && c != 0.0f) atomicAdd(&bacc, c);
    __syncthreads();
    if (threadIdx.x == 0 && bacc != 0.0f) atomicAdd(reg_out, 0.5f * bacc);
}

extern "C" void kernel_launch(void* const* d_in, const int* in_sizes, int n_in,
                              void* d_out, int out_size) {
    const int*   user_ids  = (const int*)d_in[0];
    const int*   bat_idx   = (const int*)d_in[1];
    const int*   sp_row    = (const int*)d_in[2];
    const int*   sp_col    = (const int*)d_in[3];
    const int*   bat_items = (const int*)d_in[4];
    const float* en_emb    = (const float*)d_in[5];
    const float* en_offset = (const float*)d_in[6];
    const float* de_emb    = (const float*)d_in[7];
    const float* de_bias   = (const float*)d_in[8];
    const float* user_emb  = (const float*)d_in[9];
    float* out = (float*)d_out;
    float* reg_out = (out_size > N_PAIRS) ? (out + N_PAIRS) : nullptr;

    k_init<<<(B_USERS * D_DIM + 255) / 256, 256>>>(reg_out);
    k_mask<<<NNZ_CNT / 256, 256>>>();
    k_scatter<<<(NNZ_CNT * 16) / 256, 256>>>(sp_row, sp_col, en_emb);
    k_hidden<<<(B_USERS * D_DIM) / 256, 256>>>(user_ids, user_emb, en_offset);
    k_decode<<<(N_PAIRS * 8) / 256, 256>>>(bat_idx, bat_items, de_emb, de_bias, out);
    if (reg_out) {
        k_reg<<<(REG_ROWS * 16 + 255) / 256, 256>>>(en_emb, en_offset, de_emb,
                                                    de_bias, user_emb, user_ids, reg_out);
    }
}